// round 13
// baseline (speedup 1.0000x reference)
#include <cuda_runtime.h>
#include <cuda_bf16.h>
#include <cuda_fp16.h>

#define BATCH 8
#define CH    256
#define NPOS  4096
#define IDIM  32

typedef unsigned long long u64;
typedef unsigned int u32;

__device__ __forceinline__ u64 pack2(float lo, float hi) {
    u64 r; asm("mov.b64 %0, {%1, %2};" : "=l"(r) : "f"(lo), "f"(hi)); return r;
}
__device__ __forceinline__ u64 ffma2(u64 a, u64 b, u64 c) {
    u64 d; asm("fma.rn.f32x2 %0, %1, %2, %3;" : "=l"(d) : "l"(a), "l"(b), "l"(c)); return d;
}
__device__ __forceinline__ u64 fmul2(u64 a, u64 b) {
    u64 d; asm("mul.rn.f32x2 %0, %1, %2;" : "=l"(d) : "l"(a), "l"(b)); return d;
}
__device__ __forceinline__ u64 fadd2(u64 a, u64 b) {
    u64 d; asm("add.rn.f32x2 %0, %1, %2;" : "=l"(d) : "l"(a), "l"(b)); return d;
}
__device__ __forceinline__ float2 unpack2(u64 a) {
    float2 f; asm("mov.b64 {%0, %1}, %2;" : "=f"(f.x), "=f"(f.y) : "l"(a)); return f;
}
__device__ __forceinline__ u32 bf2(float lo, float hi) {   // {lo16, hi16} packed bf16x2
    u32 r; asm("cvt.rn.bf16x2.f32 %0, %1, %2;" : "=r"(r) : "f"(hi), "f"(lo)); return r;
}
__device__ __forceinline__ u32 hf2(float lo, float hi) {   // {lo16, hi16} packed f16x2
    u32 r; asm("cvt.rn.f16x2.f32 %0, %1, %2;" : "=r"(r) : "f"(hi), "f"(lo)); return r;
}
__device__ __forceinline__ u32 smem_u32(const void* p) {
    u32 a; asm("{ .reg .u64 t; cvta.to.shared.u64 t, %1; cvt.u32.u64 %0, t; }" : "=r"(a) : "l"(p));
    return a;
}
// bf16 MMA (PV path)
__device__ __forceinline__ void mma16816(float* d, u32 a0, u32 a1, u32 a2, u32 a3,
                                         u32 b0, u32 b1) {
    asm volatile("mma.sync.aligned.m16n8k16.row.col.f32.bf16.bf16.f32 "
                 "{%0,%1,%2,%3}, {%4,%5,%6,%7}, {%8,%9}, {%0,%1,%2,%3};"
                 : "+f"(d[0]), "+f"(d[1]), "+f"(d[2]), "+f"(d[3])
                 : "r"(a0), "r"(a1), "r"(a2), "r"(a3), "r"(b0), "r"(b1));
}
// fp16 MMA (S path + qkv GEMM)
__device__ __forceinline__ void mma16816h(float* d, u32 a0, u32 a1, u32 a2, u32 a3,
                                          u32 b0, u32 b1) {
    asm volatile("mma.sync.aligned.m16n8k16.row.col.f32.f16.f16.f32 "
                 "{%0,%1,%2,%3}, {%4,%5,%6,%7}, {%8,%9}, {%0,%1,%2,%3};"
                 : "+f"(d[0]), "+f"(d[1]), "+f"(d[2]), "+f"(d[3])
                 : "r"(a0), "r"(a1), "r"(a2), "r"(a3), "r"(b0), "r"(b1));
}
__device__ __forceinline__ void cpa16(u32 dst, const void* src) {
    asm volatile("cp.async.cg.shared.global [%0], [%1], 16;" :: "r"(dst), "l"(src));
}
__device__ __forceinline__ void cpa_commit() { asm volatile("cp.async.commit_group;" ::: "memory"); }
__device__ __forceinline__ void cpa_wait0()  { asm volatile("cp.async.wait_group 0;" ::: "memory"); }
__device__ __forceinline__ void cpa_wait1()  { asm volatile("cp.async.wait_group 1;" ::: "memory"); }

// Fast exp on the FMA pipe (no MUFU)
__device__ __forceinline__ void exp_pair(float s0, float s1, float& p0, float& p1) {
    const float MAGIC = 12582912.f;   // 1.5 * 2^23
    u64 t2  = fmul2(pack2(s0, s1), pack2(1.4426950408889634f, 1.4426950408889634f));
    u64 r2  = fadd2(t2, pack2(MAGIC, MAGIC));
    u64 rm2 = fadd2(r2, pack2(-MAGIC, -MAGIC));
    u64 f2  = ffma2(rm2, pack2(-1.f, -1.f), t2);
    u64 q2  = ffma2(f2, pack2(1.3333558146e-3f, 1.3333558146e-3f),
                        pack2(9.6181291076e-3f, 9.6181291076e-3f));
    q2 = ffma2(f2, q2, pack2(5.5504108664e-2f, 5.5504108664e-2f));
    q2 = ffma2(f2, q2, pack2(2.4022650696e-1f, 2.4022650696e-1f));
    q2 = ffma2(f2, q2, pack2(6.9314718056e-1f, 6.9314718056e-1f));
    q2 = ffma2(f2, q2, pack2(1.f, 1.f));
    float2 rr = unpack2(r2);
    float2 qq = unpack2(q2);
    int e0 = (__float_as_int(rr.x) - 0x4B400000) << 23;
    int e1 = (__float_as_int(rr.y) - 0x4B400000) << 23;
    p0 = __int_as_float(__float_as_int(qq.x) + e0);
    p1 = __int_as_float(__float_as_int(qq.y) + e1);
}

// Scratch
__device__ __half g_wh[320 * CH];                     // W fp16 [320 r][256 c]
__device__ __half g_qh[BATCH * NPOS * IDIM];          // q fp16 [b][m][32 i]
__device__ __half g_kh[BATCH * NPOS * IDIM];          // k fp16 [b][n][32 i]
__device__ __nv_bfloat16 g_v[BATCH * CH * NPOS];      // v bf16 [b][c][n]

// ---------------------------------------------------------------------------
// Kernel 0: W (320 x 256) -> fp16.  grid 80, one float4 per thread.
// ---------------------------------------------------------------------------
__global__ __launch_bounds__(256, 4)
void wprep_kernel(const float* __restrict__ Wq, const float* __restrict__ Wk,
                  const float* __restrict__ Wv)
{
    const int idx4 = blockIdx.x * 256 + threadIdx.x;   // 0..20479
    int el = idx4 * 4;
    int r = el >> 8, c = el & 255;
    const float* src;
    if (r < 32)       src = Wq + r * CH + c;
    else if (r < 64)  src = Wk + (r - 32) * CH + c;
    else              src = Wv + (r - 64) * CH + c;
    float4 wv = *(const float4*)src;
    *(uint2*)((char*)g_wh + (size_t)el * 2) =
        make_uint2(hf2(wv.x, wv.y), hf2(wv.z, wv.w));
}

// ---------------------------------------------------------------------------
// Kernel 1: QKV GEMM, fp16 HMMA, x converted in-kernel.  (unchanged R12)
// ---------------------------------------------------------------------------
#define GX_PITCH 528
#define GSM_TOT  33792

__global__ __launch_bounds__(320, 2)
void qkv_gemm(const float* __restrict__ x,
              const float* __restrict__ bq, const float* __restrict__ bk,
              const float* __restrict__ bv)
{
    extern __shared__ char sm[];

    const int b    = blockIdx.y;
    const int m0   = blockIdx.x * 64;
    const int tid  = threadIdx.x;
    const int w    = tid >> 5;
    const int lane = tid & 31;
    const int lr4  = lane >> 2;
    const int lc2  = (lane & 3) * 2;
    const int rbase = w * 32;
    const bool is_qk = (w < 2);

    {
        const float* xb = x + (size_t)b * CH * NPOS;
        for (int i = tid; i < 2048; i += 320) {
            int cp = i & 127, nq = i >> 7;
            const float* p0 = xb + (size_t)(2 * cp) * NPOS + m0 + nq * 4;
            float4 a  = *(const float4*)p0;
            float4 c4 = *(const float4*)(p0 + NPOS);
            float av[4] = {a.x, a.y, a.z, a.w};
            float cv[4] = {c4.x, c4.y, c4.z, c4.w};
            #pragma unroll
            for (int e = 0; e < 4; e++)
                *(u32*)(sm + (nq * 4 + e) * GX_PITCH + cp * 4) = hf2(av[e], cv[e]);
        }
    }
    __syncthreads();

    float d[2][8][4];
    #pragma unroll
    for (int mi = 0; mi < 2; mi++)
        #pragma unroll
        for (int nb = 0; nb < 8; nb++)
            #pragma unroll
            for (int r = 0; r < 4; r++) d[mi][nb][r] = 0.f;

    const char* whb = (const char*)g_wh;
    #pragma unroll 4
    for (int ks = 0; ks < 16; ks++) {
        const int kby = ks * 32 + (lane & 3) * 4;
        u32 a[2][4];
        #pragma unroll
        for (int mi = 0; mi < 2; mi++) {
            const char* pa = whb + (size_t)(rbase + mi * 16 + lr4) * 512 + kby;
            a[mi][0] = *(const u32*)pa;
            a[mi][1] = *(const u32*)(pa + 4096);
            a[mi][2] = *(const u32*)(pa + 16);
            a[mi][3] = *(const u32*)(pa + 4096 + 16);
        }
        #pragma unroll
        for (int nb = 0; nb < 8; nb++) {
            const char* pb = sm + (nb * 8 + lr4) * GX_PITCH + kby;
            u32 b0 = *(const u32*)pb;
            u32 b1 = *(const u32*)(pb + 16);
            mma16816h(d[0][nb], a[0][0], a[0][1], a[0][2], a[0][3], b0, b1);
            mma16816h(d[1][nb], a[1][0], a[1][1], a[1][2], a[1][3], b0, b1);
        }
    }

    if (!is_qk) {
        #pragma unroll
        for (int mi = 0; mi < 2; mi++) {
            int c0 = rbase - 64 + mi * 16 + lr4;
            int c1 = c0 + 8;
            float bv0 = bv[c0], bv1 = bv[c1];
            #pragma unroll
            for (int nb = 0; nb < 8; nb++) {
                int n = m0 + nb * 8 + lc2;
                u32 w0 = bf2(d[mi][nb][0] + bv0, d[mi][nb][1] + bv0);
                u32 w1 = bf2(d[mi][nb][2] + bv1, d[mi][nb][3] + bv1);
                *(u32*)((char*)g_v + ((size_t)(b * CH + c0) * NPOS + n) * 2) = w0;
                *(u32*)((char*)g_v + ((size_t)(b * CH + c1) * NPOS + n) * 2) = w1;
            }
        }
    }

    __syncthreads();
    float* bounce = (float*)sm;
    if (is_qk) {
        #pragma unroll
        for (int mi = 0; mi < 2; mi++) {
            int r = rbase + mi * 16 + lr4;
            #pragma unroll
            for (int nb = 0; nb < 8; nb++) {
                int n = nb * 8 + lc2;
                bounce[n * 68 + r]           = d[mi][nb][0];
                bounce[(n + 1) * 68 + r]     = d[mi][nb][1];
                bounce[n * 68 + r + 8]       = d[mi][nb][2];
                bounce[(n + 1) * 68 + r + 8] = d[mi][nb][3];
            }
        }
    }
    __syncthreads();

    for (int i = tid; i < 2048; i += 320) {
        int n = i >> 5, rp = i & 31;
        float2 f = *(const float2*)(bounce + n * 68 + rp * 2);
        bool isq = (rp < 16);
        int lr = isq ? 2 * rp : 2 * rp - 32;
        float b0 = isq ? bq[lr]     : bk[lr];
        float b1 = isq ? bq[lr + 1] : bk[lr + 1];
        u32 hw = hf2(f.x + b0, f.y + b1);
        size_t base = (((size_t)b * NPOS + m0 + n) * IDIM + lr) * 2;
        if (isq) *(u32*)((char*)g_qh + base) = hw;
        else     *(u32*)((char*)g_kh + base) = hw;
    }
}

// ---------------------------------------------------------------------------
// Kernel 2: attention, channel-split 2-CTA. 256 threads (8 warps) per CTA,
// M-tile 128 q, CTA owns 128 of 256 channels. Chunk 64 keys; S duplicated.
// Warp w: S = q-group w (16 q x full 64 n, 8 t-steps); PV tile 32m x 64c
// (mb2 = (w&3)*32, cb0 = (w>>2)*64 within the CTA's 128-channel half).
// ---------------------------------------------------------------------------
#define LARR_OFF 0
#define AQ_OFF   1024                    // [128 m][80B] fp16              10240
#define AK_OFF   (AQ_OFF + 10240)        // 2 bufs x [64 n][80B] fp16      10240
#define AP_OFF   (AK_OFF + 10240)        // 2 bufs x [128 m][144B] bf16    36864
#define AV_OFF   (AP_OFF + 36864)        // 2 bufs x [128 c][144B] bf16    36864
#define ASM_TOT  (AV_OFF + 36864)        // 95232 B

// PV fused step: O[32m x 64c] += P[.,16k] * V[.,16k]^T  (bf16)
__device__ __forceinline__ void pv_step(const char* Pb, const char* Vb, int t,
        int mb2, int cb0, int lr4, int lc2, float (*o)[8][4])
{
    const int kby = (t * 16 + lc2) * 2;
    u32 a[2][4];
    #pragma unroll
    for (int mi = 0; mi < 2; mi++) {
        const char* pa = Pb + (mb2 + mi * 16 + lr4) * 144 + kby;
        a[mi][0] = *(const u32*)pa;
        a[mi][1] = *(const u32*)(pa + 8 * 144);
        a[mi][2] = *(const u32*)(pa + 16);
        a[mi][3] = *(const u32*)(pa + 8 * 144 + 16);
    }
    #pragma unroll
    for (int cj = 0; cj < 8; cj++) {
        const char* pb = Vb + (cb0 + cj * 8 + lr4) * 144 + kby;
        u32 b0 = *(const u32*)pb;
        u32 b1 = *(const u32*)(pb + 16);
        mma16816(o[0][cj], a[0][0], a[0][1], a[0][2], a[0][3], b0, b1);
        mma16816(o[1][cj], a[1][0], a[1][1], a[1][2], a[1][3], b0, b1);
    }
}

// S MMA only: S[16q x 8n] at n-block t (t=0..7) via fp16 (2 MMAs) -> regs
__device__ __forceinline__ void s_mma(const char* Kb, int t,
        int lr4, int lc2, const u32 (*ah)[4], float* d)
{
    const int nbase = t * 8;
    d[0] = d[1] = d[2] = d[3] = 0.f;
    #pragma unroll
    for (int ks = 0; ks < 2; ks++) {
        int kby = (ks * 16 + lc2) * 2;
        const char* pbh = Kb + (nbase + lr4) * 80 + kby;
        u32 b0 = *(const u32*)pbh;
        u32 b1 = *(const u32*)(pbh + 16);
        mma16816h(d, ah[ks][0], ah[ks][1], ah[ks][2], ah[ks][3], b0, b1);
    }
}

// S finish: exp + l accum + P store
__device__ __forceinline__ void s_finish(char* Pd, int t,
        int mA, int lc2, const float* d, u64& lrA2, u64& lrB2)
{
    float pA0, pA1, pB0, pB1;
    exp_pair(d[0], d[1], pA0, pA1);
    exp_pair(d[2], d[3], pB0, pB1);
    lrA2 = fadd2(lrA2, pack2(pA0, pA1));
    lrB2 = fadd2(lrB2, pack2(pB0, pB1));
    const int c0 = t * 8 + lc2;
    *(u32*)(Pd + mA * 144 + c0 * 2)       = bf2(pA0, pA1);
    *(u32*)(Pd + (mA + 8) * 144 + c0 * 2) = bf2(pB0, pB1);
}

__global__ __launch_bounds__(256, 2)
void attn_kernel(const float* __restrict__ x,
                 const float* __restrict__ gamma,
                 float* __restrict__ out)
{
    extern __shared__ char sm[];
    float* larr = (float*)(sm + LARR_OFF);
    const u32 smb = smem_u32(sm);

    const int b    = blockIdx.y;
    const int m0   = (blockIdx.x >> 1) * 128;
    const int ccta = (blockIdx.x & 1) * 128;    // CTA's channel half
    const int tid  = threadIdx.x;
    const int w    = tid >> 5;
    const int lane = tid & 31;
    const int lr4  = lane >> 2;
    const int lc2  = (lane & 3) * 2;
    const int g    = w;              // S q-group (16 queries)
    const int mb2  = (w & 3) * 32;   // PV m-block
    const int cb0  = (w >> 2) * 64;  // PV c-block (local, 0 or 64)

    const __half* qhb = g_qh + ((size_t)b * NPOS + m0) * IDIM;
    const __half* khb = g_kh + (size_t)b * NPOS * IDIM;
    const __nv_bfloat16* vb = g_v + ((size_t)(b * CH + ccta)) * NPOS;

    auto stage_K = [&](int buf, int n0) {      // 256 ops, one per thread
        int j = tid & 3, row = tid >> 2;
        cpa16(smb + AK_OFF + buf * 5120 + row * 80 + j * 16,
              khb + (size_t)(n0 + row) * IDIM + j * 8);
    };
    auto stage_V = [&](int buf, int n0) {      // [128 c][64 n]: 1024 ops
        #pragma unroll
        for (int it = 0; it < 4; it++) {
            int idx = tid + it * 256;
            int c = idx >> 3, j = idx & 7;
            cpa16(smb + AV_OFF + buf * 18432 + c * 144 + j * 16,
                  vb + (size_t)c * NPOS + n0 + j * 8);
        }
    };

    // ---- Prologue ----
    #pragma unroll
    for (int it = 0; it < 2; it++) {           // Q: 512 ops
        int idx = tid + it * 256;
        int j = idx & 3, row = idx >> 2;
        cpa16(smb + AQ_OFF + row * 80 + j * 16, qhb + (size_t)row * IDIM + j * 8);
    }
    stage_K(0, 0);
    cpa_commit();                              // G0: Q + K(0)
    stage_V(0, 0);
    stage_K(1, 64);
    cpa_commit();                              // G1: V(0) + K(1)
    cpa_wait1();                               // Q, K(0) landed
    __syncthreads();

    // Q a-frags (persistent registers, fp16)
    u32 ah[2][4];
    #pragma unroll
    for (int ks = 0; ks < 2; ks++) {
        int kby = (ks * 16 + lc2) * 2;
        const char* pah = sm + AQ_OFF + (g * 16 + lr4) * 80 + kby;
        ah[ks][0] = *(const u32*)(pah);
        ah[ks][1] = *(const u32*)(pah + 8 * 80);
        ah[ks][2] = *(const u32*)(pah + 16);
        ah[ks][3] = *(const u32*)(pah + 8 * 80 + 16);
    }

    float o[2][8][4];
    #pragma unroll
    for (int mi = 0; mi < 2; mi++)
        #pragma unroll
        for (int cj = 0; cj < 8; cj++)
            #pragma unroll
            for (int r = 0; r < 4; r++) o[mi][cj][r] = 0.f;
    u64 lrA2 = 0ull, lrB2 = 0ull;
    const int mA = g * 16 + lr4;

    float sd[2][4];

    // S(0) peeled, staggered
    #pragma unroll
    for (int t = 0; t < 8; t++) {
        s_mma(sm + AK_OFF, t, lr4, lc2, ah, sd[t & 1]);
        if (t > 0) s_finish(sm + AP_OFF, t - 1, mA, lc2, sd[(t - 1) & 1], lrA2, lrB2);
    }
    s_finish(sm + AP_OFF, 7, mA, lc2, sd[1], lrA2, lrB2);
    cpa_wait0();                               // V(0), K(1) landed
    __syncthreads();                           // P(0) visible

    // ---- Main loop: iter kk does PV(kk) + S(kk+1), exp staggered ----
    #pragma unroll 1
    for (int kk = 0; kk < 63; kk++) {
        stage_V((kk + 1) & 1, (kk + 1) * 64);
        if (kk < 62) stage_K(kk & 1, (kk + 2) * 64);
        cpa_commit();

        const char* Pb = sm + AP_OFF + (kk & 1) * 18432;
        const char* Vb = sm + AV_OFF + (kk & 1) * 18432;
        const char* Kb = sm + AK_OFF + ((kk + 1) & 1) * 5120;
        char*       Pd = sm + AP_OFF + ((kk + 1) & 1) * 18432;

        #pragma unroll
        for (int t = 0; t < 4; t++) {
            pv_step(Pb, Vb, t, mb2, cb0, lr4, lc2, o);
            s_mma(Kb, 2 * t, lr4, lc2, ah, sd[0]);
            if (t > 0) s_finish(Pd, 2 * t - 1, mA, lc2, sd[1], lrA2, lrB2);
            s_mma(Kb, 2 * t + 1, lr4, lc2, ah, sd[1]);
            s_finish(Pd, 2 * t, mA, lc2, sd[0], lrA2, lrB2);
        }
        s_finish(Pd, 7, mA, lc2, sd[1], lrA2, lrB2);
        cpa_wait0();
        __syncthreads();
    }

    // Final PV(63)
    #pragma unroll
    for (int t = 0; t < 4; t++)
        pv_step(sm + AP_OFF + 18432, sm + AV_OFF + 18432, t, mb2, cb0, lr4, lc2, o);

    // ---- l reduction (within quad lanes; warp covers all keys) ----
    {
        float2 fa = unpack2(lrA2);
        float2 fb = unpack2(lrB2);
        float lA = fa.x + fa.y;
        float lB = fb.x + fb.y;
        #pragma unroll
        for (int off = 1; off <= 2; off <<= 1) {
            lA += __shfl_xor_sync(0xffffffffu, lA, off);
            lB += __shfl_xor_sync(0xffffffffu, lB, off);
        }
        if ((lane & 3) == 0) {
            larr[g * 16 + lr4]     = lA;
            larr[g * 16 + lr4 + 8] = lB;
        }
    }
    __syncthreads();

    // ---- Epilogue: CTA's 128 channels ----
    const float gm = gamma[0];
    const size_t gbase = (size_t)b * CH * NPOS + m0;
    #pragma unroll
    for (int mi = 0; mi < 2; mi++) {
        const int mAe = mb2 + mi * 16 + lr4;
        const int mBe = mAe + 8;
        const float recA = gm / larr[mAe];
        const float recB = gm / larr[mBe];
        #pragma unroll
        for (int cj = 0; cj < 8; cj++) {
            const int c0 = ccta + cb0 + cj * 8 + lc2;
            size_t gi0 = gbase + (size_t)c0 * NPOS;
            out[gi0 + mAe]        = o[mi][cj][0] * recA + x[gi0 + mAe];
            out[gi0 + NPOS + mAe] = o[mi][cj][1] * recA + x[gi0 + NPOS + mAe];
            out[gi0 + mBe]        = o[mi][cj][2] * recB + x[gi0 + mBe];
            out[gi0 + NPOS + mBe] = o[mi][cj][3] * recB + x[gi0 + NPOS + mBe];
        }
    }
}

// ---------------------------------------------------------------------------
extern "C" void kernel_launch(void* const* d_in, const int* in_sizes, int n_in,
                              void* d_out, int out_size)
{
    const float* x     = (const float*)d_in[0];
    const float* Wq    = (const float*)d_in[1];
    const float* bq    = (const float*)d_in[2];
    const float* Wk    = (const float*)d_in[3];
    const float* bk    = (const float*)d_in[4];
    const float* Wv    = (const float*)d_in[5];
    const float* bv    = (const float*)d_in[6];
    const float* gamma = (const float*)d_in[7];
    float* out = (float*)d_out;

    cudaFuncSetAttribute(qkv_gemm,    cudaFuncAttributeMaxDynamicSharedMemorySize, GSM_TOT);
    cudaFuncSetAttribute(attn_kernel, cudaFuncAttributeMaxDynamicSharedMemorySize, ASM_TOT);

    wprep_kernel<<<80, 256>>>(Wq, Wk, Wv);
    qkv_gemm<<<dim3(64, 8), 320, GSM_TOT>>>(x, bq, bk, bv);
    attn_kernel<<<dim3(64, 8), 256, ASM_TOT>>>(x, gamma, out);
}

// round 15
// speedup vs baseline: 1.1782x; 1.1782x over previous
#include <cuda_runtime.h>
#include <cuda_bf16.h>
#include <cuda_fp16.h>

#define BATCH 8
#define CH    256
#define NPOS  4096
#define IDIM  32

typedef unsigned long long u64;
typedef unsigned int u32;

__device__ __forceinline__ u64 pack2(float lo, float hi) {
    u64 r; asm("mov.b64 %0, {%1, %2};" : "=l"(r) : "f"(lo), "f"(hi)); return r;
}
__device__ __forceinline__ u64 ffma2(u64 a, u64 b, u64 c) {
    u64 d; asm("fma.rn.f32x2 %0, %1, %2, %3;" : "=l"(d) : "l"(a), "l"(b), "l"(c)); return d;
}
__device__ __forceinline__ u64 fmul2(u64 a, u64 b) {
    u64 d; asm("mul.rn.f32x2 %0, %1, %2;" : "=l"(d) : "l"(a), "l"(b)); return d;
}
__device__ __forceinline__ u64 fadd2(u64 a, u64 b) {
    u64 d; asm("add.rn.f32x2 %0, %1, %2;" : "=l"(d) : "l"(a), "l"(b)); return d;
}
__device__ __forceinline__ float2 unpack2(u64 a) {
    float2 f; asm("mov.b64 {%0, %1}, %2;" : "=f"(f.x), "=f"(f.y) : "l"(a)); return f;
}
__device__ __forceinline__ u32 bf2(float lo, float hi) {   // {lo16, hi16} packed bf16x2
    u32 r; asm("cvt.rn.bf16x2.f32 %0, %1, %2;" : "=r"(r) : "f"(hi), "f"(lo)); return r;
}
__device__ __forceinline__ u32 hf2(float lo, float hi) {   // {lo16, hi16} packed f16x2
    u32 r; asm("cvt.rn.f16x2.f32 %0, %1, %2;" : "=r"(r) : "f"(hi), "f"(lo)); return r;
}
__device__ __forceinline__ u32 smem_u32(const void* p) {
    u32 a; asm("{ .reg .u64 t; cvta.to.shared.u64 t, %1; cvt.u32.u64 %0, t; }" : "=r"(a) : "l"(p));
    return a;
}
// bf16 MMA (PV path)
__device__ __forceinline__ void mma16816(float* d, u32 a0, u32 a1, u32 a2, u32 a3,
                                         u32 b0, u32 b1) {
    asm volatile("mma.sync.aligned.m16n8k16.row.col.f32.bf16.bf16.f32 "
                 "{%0,%1,%2,%3}, {%4,%5,%6,%7}, {%8,%9}, {%0,%1,%2,%3};"
                 : "+f"(d[0]), "+f"(d[1]), "+f"(d[2]), "+f"(d[3])
                 : "r"(a0), "r"(a1), "r"(a2), "r"(a3), "r"(b0), "r"(b1));
}
// fp16 MMA (S path + qkv GEMM)
__device__ __forceinline__ void mma16816h(float* d, u32 a0, u32 a1, u32 a2, u32 a3,
                                          u32 b0, u32 b1) {
    asm volatile("mma.sync.aligned.m16n8k16.row.col.f32.f16.f16.f32 "
                 "{%0,%1,%2,%3}, {%4,%5,%6,%7}, {%8,%9}, {%0,%1,%2,%3};"
                 : "+f"(d[0]), "+f"(d[1]), "+f"(d[2]), "+f"(d[3])
                 : "r"(a0), "r"(a1), "r"(a2), "r"(a3), "r"(b0), "r"(b1));
}
__device__ __forceinline__ void cpa16(u32 dst, const void* src) {
    asm volatile("cp.async.cg.shared.global [%0], [%1], 16;" :: "r"(dst), "l"(src));
}
__device__ __forceinline__ void cpa_commit() { asm volatile("cp.async.commit_group;" ::: "memory"); }
__device__ __forceinline__ void cpa_wait0()  { asm volatile("cp.async.wait_group 0;" ::: "memory"); }

// Fast exp on the FMA pipe (no MUFU)
__device__ __forceinline__ void exp_pair(float s0, float s1, float& p0, float& p1) {
    const float MAGIC = 12582912.f;   // 1.5 * 2^23
    u64 t2  = fmul2(pack2(s0, s1), pack2(1.4426950408889634f, 1.4426950408889634f));
    u64 r2  = fadd2(t2, pack2(MAGIC, MAGIC));
    u64 rm2 = fadd2(r2, pack2(-MAGIC, -MAGIC));
    u64 f2  = ffma2(rm2, pack2(-1.f, -1.f), t2);
    u64 q2  = ffma2(f2, pack2(1.3333558146e-3f, 1.3333558146e-3f),
                        pack2(9.6181291076e-3f, 9.6181291076e-3f));
    q2 = ffma2(f2, q2, pack2(5.5504108664e-2f, 5.5504108664e-2f));
    q2 = ffma2(f2, q2, pack2(2.4022650696e-1f, 2.4022650696e-1f));
    q2 = ffma2(f2, q2, pack2(6.9314718056e-1f, 6.9314718056e-1f));
    q2 = ffma2(f2, q2, pack2(1.f, 1.f));
    float2 rr = unpack2(r2);
    float2 qq = unpack2(q2);
    int e0 = (__float_as_int(rr.x) - 0x4B400000) << 23;
    int e1 = (__float_as_int(rr.y) - 0x4B400000) << 23;
    p0 = __int_as_float(__float_as_int(qq.x) + e0);
    p1 = __int_as_float(__float_as_int(qq.y) + e1);
}

// Scratch
__device__ __half g_wh[320 * CH];                     // W fp16 [320 r][256 c]
__device__ __half g_qh[BATCH * NPOS * IDIM];          // q fp16 [b][m][32 i]
__device__ __half g_kh[BATCH * NPOS * IDIM];          // k fp16 [b][n][32 i]
__device__ __nv_bfloat16 g_v[BATCH * CH * NPOS];      // v bf16 [b][c][n]

// ---------------------------------------------------------------------------
// Kernel 0: W (320 x 256) -> fp16.  grid 80, one float4 per thread.
// ---------------------------------------------------------------------------
__global__ __launch_bounds__(256, 4)
void wprep_kernel(const float* __restrict__ Wq, const float* __restrict__ Wk,
                  const float* __restrict__ Wv)
{
    const int idx4 = blockIdx.x * 256 + threadIdx.x;
    int el = idx4 * 4;
    int r = el >> 8, c = el & 255;
    const float* src;
    if (r < 32)       src = Wq + r * CH + c;
    else if (r < 64)  src = Wk + (r - 32) * CH + c;
    else              src = Wv + (r - 64) * CH + c;
    float4 wv = *(const float4*)src;
    *(uint2*)((char*)g_wh + (size_t)el * 2) =
        make_uint2(hf2(wv.x, wv.y), hf2(wv.z, wv.w));
}

// ---------------------------------------------------------------------------
// Kernel 1: QKV GEMM, fp16 HMMA, x converted in-kernel.  (unchanged R12)
// ---------------------------------------------------------------------------
#define GX_PITCH 528
#define GSM_TOT  33792

__global__ __launch_bounds__(320, 2)
void qkv_gemm(const float* __restrict__ x,
              const float* __restrict__ bq, const float* __restrict__ bk,
              const float* __restrict__ bv)
{
    extern __shared__ char sm[];

    const int b    = blockIdx.y;
    const int m0   = blockIdx.x * 64;
    const int tid  = threadIdx.x;
    const int w    = tid >> 5;
    const int lane = tid & 31;
    const int lr4  = lane >> 2;
    const int lc2  = (lane & 3) * 2;
    const int rbase = w * 32;
    const bool is_qk = (w < 2);

    {
        const float* xb = x + (size_t)b * CH * NPOS;
        for (int i = tid; i < 2048; i += 320) {
            int cp = i & 127, nq = i >> 7;
            const float* p0 = xb + (size_t)(2 * cp) * NPOS + m0 + nq * 4;
            float4 a  = *(const float4*)p0;
            float4 c4 = *(const float4*)(p0 + NPOS);
            float av[4] = {a.x, a.y, a.z, a.w};
            float cv[4] = {c4.x, c4.y, c4.z, c4.w};
            #pragma unroll
            for (int e = 0; e < 4; e++)
                *(u32*)(sm + (nq * 4 + e) * GX_PITCH + cp * 4) = hf2(av[e], cv[e]);
        }
    }
    __syncthreads();

    float d[2][8][4];
    #pragma unroll
    for (int mi = 0; mi < 2; mi++)
        #pragma unroll
        for (int nb = 0; nb < 8; nb++)
            #pragma unroll
            for (int r = 0; r < 4; r++) d[mi][nb][r] = 0.f;

    const char* whb = (const char*)g_wh;
    #pragma unroll 4
    for (int ks = 0; ks < 16; ks++) {
        const int kby = ks * 32 + (lane & 3) * 4;
        u32 a[2][4];
        #pragma unroll
        for (int mi = 0; mi < 2; mi++) {
            const char* pa = whb + (size_t)(rbase + mi * 16 + lr4) * 512 + kby;
            a[mi][0] = *(const u32*)pa;
            a[mi][1] = *(const u32*)(pa + 4096);
            a[mi][2] = *(const u32*)(pa + 16);
            a[mi][3] = *(const u32*)(pa + 4096 + 16);
        }
        #pragma unroll
        for (int nb = 0; nb < 8; nb++) {
            const char* pb = sm + (nb * 8 + lr4) * GX_PITCH + kby;
            u32 b0 = *(const u32*)pb;
            u32 b1 = *(const u32*)(pb + 16);
            mma16816h(d[0][nb], a[0][0], a[0][1], a[0][2], a[0][3], b0, b1);
            mma16816h(d[1][nb], a[1][0], a[1][1], a[1][2], a[1][3], b0, b1);
        }
    }

    if (!is_qk) {
        #pragma unroll
        for (int mi = 0; mi < 2; mi++) {
            int c0 = rbase - 64 + mi * 16 + lr4;
            int c1 = c0 + 8;
            float bv0 = bv[c0], bv1 = bv[c1];
            #pragma unroll
            for (int nb = 0; nb < 8; nb++) {
                int n = m0 + nb * 8 + lc2;
                u32 w0 = bf2(d[mi][nb][0] + bv0, d[mi][nb][1] + bv0);
                u32 w1 = bf2(d[mi][nb][2] + bv1, d[mi][nb][3] + bv1);
                *(u32*)((char*)g_v + ((size_t)(b * CH + c0) * NPOS + n) * 2) = w0;
                *(u32*)((char*)g_v + ((size_t)(b * CH + c1) * NPOS + n) * 2) = w1;
            }
        }
    }

    __syncthreads();
    float* bounce = (float*)sm;
    if (is_qk) {
        #pragma unroll
        for (int mi = 0; mi < 2; mi++) {
            int r = rbase + mi * 16 + lr4;
            #pragma unroll
            for (int nb = 0; nb < 8; nb++) {
                int n = nb * 8 + lc2;
                bounce[n * 68 + r]           = d[mi][nb][0];
                bounce[(n + 1) * 68 + r]     = d[mi][nb][1];
                bounce[n * 68 + r + 8]       = d[mi][nb][2];
                bounce[(n + 1) * 68 + r + 8] = d[mi][nb][3];
            }
        }
    }
    __syncthreads();

    for (int i = tid; i < 2048; i += 320) {
        int n = i >> 5, rp = i & 31;
        float2 f = *(const float2*)(bounce + n * 68 + rp * 2);
        bool isq = (rp < 16);
        int lr = isq ? 2 * rp : 2 * rp - 32;
        float b0 = isq ? bq[lr]     : bk[lr];
        float b1 = isq ? bq[lr + 1] : bk[lr + 1];
        u32 hw = hf2(f.x + b0, f.y + b1);
        size_t base = (((size_t)b * NPOS + m0 + n) * IDIM + lr) * 2;
        if (isq) *(u32*)((char*)g_qh + base) = hw;
        else     *(u32*)((char*)g_kh + base) = hw;
    }
}

// ---------------------------------------------------------------------------
// Kernel 2: attention, warp-specialized. 640 threads:
//   warps 0-15  = consumers: pure PV (32m x 64c tile each, O in regs).
//   warps 16-19 = producers: all staging (cp.async) + S (32q x 64k each)
//                 + exp + P stores + l accumulation.
// M-tile 128 q, chunk 64 keys. P/V/K double-buffered. 1 barrier per chunk.
// ---------------------------------------------------------------------------
#define LARR_OFF 0                       // [128] f32
#define AQ_OFF   1024                    // [128 m][80B] fp16              10240
#define AK_OFF   (AQ_OFF + 10240)        // 2 bufs x [64 n][80B] fp16      10240
#define AP_OFF   (AK_OFF + 10240)        // 2 bufs x [128 m][144B] bf16    36864
#define AV_OFF   (AP_OFF + 36864)        // 2 bufs x [256 c][144B] bf16    73728
#define ASM_TOT  (AV_OFF + 73728)        // 132096 B

// PV step: O[32m x 64c] += P[.,16k] * V[.,16k]^T  (bf16)
__device__ __forceinline__ void pv_step(const char* Pb, const char* Vb, int t,
        int mb2, int cb0, int lr4, int lc2, float (*o)[8][4])
{
    const int kby = (t * 16 + lc2) * 2;
    u32 a[2][4];
    #pragma unroll
    for (int mi = 0; mi < 2; mi++) {
        const char* pa = Pb + (mb2 + mi * 16 + lr4) * 144 + kby;
        a[mi][0] = *(const u32*)pa;
        a[mi][1] = *(const u32*)(pa + 8 * 144);
        a[mi][2] = *(const u32*)(pa + 16);
        a[mi][3] = *(const u32*)(pa + 8 * 144 + 16);
    }
    #pragma unroll
    for (int cj = 0; cj < 8; cj++) {
        const char* pb = Vb + (cb0 + cj * 8 + lr4) * 144 + kby;
        u32 b0 = *(const u32*)pb;
        u32 b1 = *(const u32*)(pb + 16);
        mma16816(o[0][cj], a[0][0], a[0][1], a[0][2], a[0][3], b0, b1);
        mma16816(o[1][cj], a[1][0], a[1][1], a[1][2], a[1][3], b0, b1);
    }
}

// Producer S finish: exp + l accum + P store
__device__ __forceinline__ void s_finish_p(char* Pd, int t, int mi,
        int wp, int lr4, int lc2, const float* d, u64* lr2)
{
    float pA0, pA1, pB0, pB1;
    exp_pair(d[0], d[1], pA0, pA1);
    exp_pair(d[2], d[3], pB0, pB1);
    lr2[mi * 2]     = fadd2(lr2[mi * 2],     pack2(pA0, pA1));
    lr2[mi * 2 + 1] = fadd2(lr2[mi * 2 + 1], pack2(pB0, pB1));
    const int mA = wp * 32 + mi * 16 + lr4;
    const int c0 = t * 8 + lc2;
    *(u32*)(Pd + mA * 144 + c0 * 2)       = bf2(pA0, pA1);
    *(u32*)(Pd + (mA + 8) * 144 + c0 * 2) = bf2(pB0, pB1);
}

// Producer S for one chunk: 32q x 64k, exp staggered one subtile behind.
__device__ __forceinline__ void s_chunk(const char* Kb, char* Pd,
        int wp, int lr4, int lc2, const u32 ah[2][2][4], u64* lr2)
{
    float sdb[2][4];
    int pt = 0, pmi = 0;
    #pragma unroll
    for (int t = 0; t < 8; t++) {
        u32 kb[2][2];
        #pragma unroll
        for (int ks = 0; ks < 2; ks++) {
            const char* pbh = Kb + (t * 8 + lr4) * 80 + (ks * 16 + lc2) * 2;
            kb[ks][0] = *(const u32*)pbh;
            kb[ks][1] = *(const u32*)(pbh + 16);
        }
        #pragma unroll
        for (int mi = 0; mi < 2; mi++) {
            const int st = t * 2 + mi;
            float* dc = sdb[st & 1];
            dc[0] = dc[1] = dc[2] = dc[3] = 0.f;
            mma16816h(dc, ah[mi][0][0], ah[mi][0][1], ah[mi][0][2], ah[mi][0][3],
                      kb[0][0], kb[0][1]);
            mma16816h(dc, ah[mi][1][0], ah[mi][1][1], ah[mi][1][2], ah[mi][1][3],
                      kb[1][0], kb[1][1]);
            if (st > 0) s_finish_p(Pd, pt, pmi, wp, lr4, lc2, sdb[(st - 1) & 1], lr2);
            pt = t; pmi = mi;
        }
    }
    s_finish_p(Pd, 7, 1, wp, lr4, lc2, sdb[1], lr2);
}

__global__ __launch_bounds__(640, 1)
void attn_kernel(const float* __restrict__ x,
                 const float* __restrict__ gamma,
                 float* __restrict__ out)
{
    extern __shared__ char sm[];
    float* larr = (float*)(sm + LARR_OFF);
    const u32 smb = smem_u32(sm);

    const int b    = blockIdx.y;
    const int m0   = blockIdx.x * 128;
    const int tid  = threadIdx.x;
    const int w    = tid >> 5;
    const int lane = tid & 31;
    const int lr4  = lane >> 2;
    const int lc2  = (lane & 3) * 2;

    if (w < 16) {
        // ================= CONSUMER: pure PV =================
        const int mb2 = (w & 3) * 32;
        const int cb0 = (w >> 2) * 64;

        float o[2][8][4];
        #pragma unroll
        for (int mi = 0; mi < 2; mi++)
            #pragma unroll
            for (int cj = 0; cj < 8; cj++)
                #pragma unroll
                for (int r = 0; r < 4; r++) o[mi][cj][r] = 0.f;

        __syncthreads();   // #1: staging visible (unused here)
        __syncthreads();   // #2: P(0) ready

        #pragma unroll 1
        for (int kk = 0; kk < 64; kk++) {
            const char* Pb = sm + AP_OFF + (kk & 1) * 18432;
            const char* Vb = sm + AV_OFF + (kk & 1) * 36864;
            #pragma unroll
            for (int t = 0; t < 4; t++)
                pv_step(Pb, Vb, t, mb2, cb0, lr4, lc2, o);
            __syncthreads();
        }
        __syncthreads();   // final: larr written

        // Epilogue
        const float gm = gamma[0];
        const size_t gbase = (size_t)b * CH * NPOS + m0;
        #pragma unroll
        for (int mi = 0; mi < 2; mi++) {
            const int mAe = mb2 + mi * 16 + lr4;
            const int mBe = mAe + 8;
            const float recA = gm / larr[mAe];
            const float recB = gm / larr[mBe];
            #pragma unroll
            for (int cj = 0; cj < 8; cj++) {
                const int c0 = cb0 + cj * 8 + lc2;
                size_t gi0 = gbase + (size_t)c0 * NPOS;
                out[gi0 + mAe]        = o[mi][cj][0] * recA + x[gi0 + mAe];
                out[gi0 + NPOS + mAe] = o[mi][cj][1] * recA + x[gi0 + NPOS + mAe];
                out[gi0 + mBe]        = o[mi][cj][2] * recB + x[gi0 + mBe];
                out[gi0 + NPOS + mBe] = o[mi][cj][3] * recB + x[gi0 + NPOS + mBe];
            }
        }
    } else {
        // ================= PRODUCER: staging + S + exp =================
        const int wp   = w - 16;        // 0..3: owns queries wp*32..+31
        const int ptid = tid - 512;     // 0..127

        const __half* qhb = g_qh + ((size_t)b * NPOS + m0) * IDIM;
        const __half* khb = g_kh + (size_t)b * NPOS * IDIM;
        const __nv_bfloat16* vb = g_v + (size_t)b * CH * NPOS;

        auto stage_K = [&](int buf, int n0) {
            #pragma unroll
            for (int it = 0; it < 2; it++) {
                int idx = ptid + it * 128;          // 256 ops: [64 n][4 j]
                int j = idx & 3, row = idx >> 2;
                cpa16(smb + AK_OFF + buf * 5120 + row * 80 + j * 16,
                      khb + (size_t)(n0 + row) * IDIM + j * 8);
            }
        };
        auto stage_V = [&](int buf, int n0) {
            #pragma unroll
            for (int it = 0; it < 16; it++) {
                int idx = ptid + it * 128;          // 2048 ops: [256 c][8 j]
                int c = idx >> 3, j = idx & 7;
                cpa16(smb + AV_OFF + buf * 36864 + c * 144 + j * 16,
                      vb + (size_t)c * NPOS + n0 + j * 8);
            }
        };

        // Prologue staging: Q (512 ops -> 4 iters of 128), K(0), V(0), K(1)
        #pragma unroll
        for (int it = 0; it < 4; it++) {
            int idx = ptid + it * 128;              // 0..511
            int j = idx & 3, row = idx >> 2;        // row 0..127
            cpa16(smb + AQ_OFF + row * 80 + j * 16, qhb + (size_t)row * IDIM + j * 8);
        }
        stage_K(0, 0);
        stage_V(0, 0);
        stage_K(1, 64);
        cpa_commit();
        cpa_wait0();
        __syncthreads();   // #1: Q/K0/V0/K1 visible block-wide

        // Q a-frags for 32 queries (2 m-blocks), fp16, persistent
        u32 ah[2][2][4];
        #pragma unroll
        for (int mi = 0; mi < 2; mi++)
            #pragma unroll
            for (int ks = 0; ks < 2; ks++) {
                const char* pah = sm + AQ_OFF + (wp * 32 + mi * 16 + lr4) * 80
                                + (ks * 16 + lc2) * 2;
                ah[mi][ks][0] = *(const u32*)(pah);
                ah[mi][ks][1] = *(const u32*)(pah + 8 * 80);
                ah[mi][ks][2] = *(const u32*)(pah + 16);
                ah[mi][ks][3] = *(const u32*)(pah + 8 * 80 + 16);
            }

        u64 lr2[4] = {0ull, 0ull, 0ull, 0ull};

        // S(0) -> P(0)
        s_chunk(sm + AK_OFF, sm + AP_OFF, wp, lr4, lc2, ah, lr2);
        __syncthreads();   // #2: P(0) ready

        #pragma unroll 1
        for (int kk = 0; kk < 64; kk++) {
            if (kk < 63) stage_V((kk + 1) & 1, (kk + 1) * 64);
            if (kk < 62) stage_K(kk & 1, (kk + 2) * 64);
            if (kk < 63) {
                cpa_commit();
                // S(kk+1): K buf (kk+1)&1 -> P buf (kk+1)&1
                s_chunk(sm + AK_OFF + ((kk + 1) & 1) * 5120,
                        sm + AP_OFF + ((kk + 1) & 1) * 18432,
                        wp, lr4, lc2, ah, lr2);
                cpa_wait0();
            }
            __syncthreads();
        }

        // l reduction: lanes lane&3 share rows
        #pragma unroll
        for (int mi = 0; mi < 2; mi++) {
            float2 fa = unpack2(lr2[mi * 2]);
            float2 fb = unpack2(lr2[mi * 2 + 1]);
            float lA = fa.x + fa.y;
            float lB = fb.x + fb.y;
            #pragma unroll
            for (int off = 1; off <= 2; off <<= 1) {
                lA += __shfl_xor_sync(0xffffffffu, lA, off);
                lB += __shfl_xor_sync(0xffffffffu, lB, off);
            }
            if ((lane & 3) == 0) {
                larr[wp * 32 + mi * 16 + lr4]     = lA;
                larr[wp * 32 + mi * 16 + lr4 + 8] = lB;
            }
        }
        __syncthreads();   // final: larr visible to consumers
    }
}

// ---------------------------------------------------------------------------
extern "C" void kernel_launch(void* const* d_in, const int* in_sizes, int n_in,
                              void* d_out, int out_size)
{
    const float* x     = (const float*)d_in[0];
    const float* Wq    = (const float*)d_in[1];
    const float* bq    = (const float*)d_in[2];
    const float* Wk    = (const float*)d_in[3];
    const float* bk    = (const float*)d_in[4];
    const float* Wv    = (const float*)d_in[5];
    const float* bv    = (const float*)d_in[6];
    const float* gamma = (const float*)d_in[7];
    float* out = (float*)d_out;

    cudaFuncSetAttribute(qkv_gemm,    cudaFuncAttributeMaxDynamicSharedMemorySize, GSM_TOT);
    cudaFuncSetAttribute(attn_kernel, cudaFuncAttributeMaxDynamicSharedMemorySize, ASM_TOT);

    wprep_kernel<<<80, 256>>>(Wq, Wk, Wv);
    qkv_gemm<<<dim3(64, 8), 320, GSM_TOT>>>(x, bq, bk, bv);
    attn_kernel<<<dim3(32, 8), 640, ASM_TOT>>>(x, gamma, out);
}